// round 6
// baseline (speedup 1.0000x reference)
#include <cuda_runtime.h>
#include <cuda_bf16.h>

// GaussianSmoother: out[b,n] = sum_t x[b,t,n] * k[t]
// x: [B=64, T=2048, N=1024] fp32.
//
// R1: Gaussian truncation + analytic normalization Z = sigma*sqrt(2pi).
// R2: tap-split across thread groups + smem reduce.
// R3: float4 loads (LDG.128).
// R5 findings: (a) rel_err tracks truncated tail mass ~1:1, so W=80
//     (4 sigma, tail 6.7e-5) keeps 15x margin under 1e-3. 161 taps.
//     (b) 512 CTAs / 148 SMs = 15.6% straggler tail (4-vs-3 CTAs/SM).
//     Fix: 1024 CTAs x 128 thr -> 7/6.92 = 1.2% tail; 20 taps/thread
//     restores deep per-thread MLP.

#define B_DIM 64
#define T_DIM 2048
#define N_DIM 1024
#define CENTER 1024
#define W 80
#define TAPS (2 * W + 1)   // 161
#define SIGMA 20.0f

// 1 / (sigma * sqrt(2*pi)) for sigma = 20  (Z over full 2048 taps equals
// sigma*sqrt(2pi) to ~e^-7800 by Poisson summation)
#define INV_Z 0.019947114020071634f

#define BLOCK_THREADS 128
#define VEC_PER_BLOCK 16          // 16 float4 = 64 n-values per block
#define GROUPS 8
#define TAPS_PER_GROUP 20         // 8*20 = 160; last group takes tap 160
#define N_VEC (N_DIM / 4)         // 256 float4 per (b, t) row

__global__ __launch_bounds__(BLOCK_THREADS) void gaussian_smooth_kernel(
    const float4* __restrict__ x, float4* __restrict__ out)
{
    __shared__ float k[TAPS];
    __shared__ float4 partial[GROUPS - 1][VEC_PER_BLOCK];

    int tid = threadIdx.x;

    // Build normalized Gaussian weights (once per block).
    for (int i = tid; i < TAPS; i += BLOCK_THREADS) {
        float d = (float)(i - W) * (1.0f / SIGMA);
        k[i] = expf(-0.5f * d * d) * INV_Z;
    }
    __syncthreads();

    int nl = tid & (VEC_PER_BLOCK - 1);   // vec4 lane within block
    int g  = tid >> 4;                    // tap-group 0..7

    int vidx = blockIdx.x * VEC_PER_BLOCK + nl;  // global vec4 index [0, 16384)
    int b  = vidx >> 8;                    // vidx / N_VEC
    int nv = vidx & (N_VEC - 1);           // vidx % N_VEC

    int t0 = g * TAPS_PER_GROUP;

    const float4* p = x + (size_t)b * T_DIM * N_VEC
                        + (size_t)(CENTER - W + t0) * N_VEC
                        + nv;

    float4 acc = make_float4(0.f, 0.f, 0.f, 0.f);
    #pragma unroll
    for (int i = 0; i < TAPS_PER_GROUP; i++) {
        float4 v = p[(size_t)i * N_VEC];
        float  w = k[t0 + i];
        acc.x += v.x * w;
        acc.y += v.y * w;
        acc.z += v.z * w;
        acc.w += v.w * w;
    }
    // leftover tap (161 = 8*20 + 1) handled by the last group
    if (g == GROUPS - 1) {
        float4 v = p[(size_t)TAPS_PER_GROUP * N_VEC];
        float  w = k[TAPS - 1];
        acc.x += v.x * w;
        acc.y += v.y * w;
        acc.z += v.z * w;
        acc.w += v.w * w;
    }

    if (g > 0) {
        partial[g - 1][nl] = acc;
    }
    __syncthreads();

    if (g == 0) {
        #pragma unroll
        for (int j = 0; j < GROUPS - 1; j++) {
            float4 v = partial[j][nl];
            acc.x += v.x;
            acc.y += v.y;
            acc.z += v.z;
            acc.w += v.w;
        }
        out[vidx] = acc;
    }
}

extern "C" void kernel_launch(void* const* d_in, const int* in_sizes, int n_in,
                              void* d_out, int out_size)
{
    const float4* x = (const float4*)d_in[0];
    float4* out = (float4*)d_out;

    const int blocks = (B_DIM * N_DIM / 4) / VEC_PER_BLOCK;   // 1024

    gaussian_smooth_kernel<<<blocks, BLOCK_THREADS>>>(x, out);
}

// round 7
// speedup vs baseline: 1.0332x; 1.0332x over previous
#include <cuda_runtime.h>
#include <cuda_bf16.h>

// GaussianSmoother: out[b,n] = sum_t x[b,t,n] * k[t]
// x: [B=64, T=2048, N=1024] fp32.
//
// R1: Gaussian truncation + analytic normalization Z = sigma*sqrt(2pi).
// R2: tap-split across thread groups + smem reduce.
// R3: float4 loads (LDG.128).
// R5: W=80 (4 sigma) safe: rel_err ~= tail mass = 6.7e-5, 15x margin.
// R6 post-mortem: 128-thr blocks halved warps/SM (28, occ 41%) -> BW
//     dropped; per-thread MLP is reg-capped at ~6-8, so AGGREGATE warp
//     count is the binding term. Fix: 1024 CTAs x 256 thr = 262144
//     threads (55 warps/SM, R5 level) AND 1.2% wave tail (R6 level).
//     16 vec4-lanes x 16 tap-groups of 10 taps (+1 leftover).

#define B_DIM 64
#define T_DIM 2048
#define N_DIM 1024
#define CENTER 1024
#define W 80
#define TAPS (2 * W + 1)   // 161
#define SIGMA 20.0f

// 1 / (sigma * sqrt(2*pi)) for sigma = 20  (Z over full 2048 taps equals
// sigma*sqrt(2pi) to ~e^-7800 by Poisson summation)
#define INV_Z 0.019947114020071634f

#define BLOCK_THREADS 256
#define VEC_PER_BLOCK 16          // 16 float4 = 64 n-values per block
#define GROUPS 16
#define TAPS_PER_GROUP 10         // 16*10 = 160; last group takes tap 160
#define N_VEC (N_DIM / 4)         // 256 float4 per (b, t) row

__global__ __launch_bounds__(BLOCK_THREADS) void gaussian_smooth_kernel(
    const float4* __restrict__ x, float4* __restrict__ out)
{
    __shared__ float k[TAPS];
    __shared__ float4 partial[GROUPS - 1][VEC_PER_BLOCK];

    int tid = threadIdx.x;

    // Build normalized Gaussian weights (once per block).
    for (int i = tid; i < TAPS; i += BLOCK_THREADS) {
        float d = (float)(i - W) * (1.0f / SIGMA);
        k[i] = expf(-0.5f * d * d) * INV_Z;
    }
    __syncthreads();

    int nl = tid & (VEC_PER_BLOCK - 1);   // vec4 lane within block
    int g  = tid >> 4;                    // tap-group 0..15

    int vidx = blockIdx.x * VEC_PER_BLOCK + nl;  // global vec4 index [0, 16384)
    int b  = vidx >> 8;                    // vidx / N_VEC
    int nv = vidx & (N_VEC - 1);           // vidx % N_VEC

    int t0 = g * TAPS_PER_GROUP;

    const float4* p = x + (size_t)b * T_DIM * N_VEC
                        + (size_t)(CENTER - W + t0) * N_VEC
                        + nv;

    float4 acc = make_float4(0.f, 0.f, 0.f, 0.f);
    #pragma unroll
    for (int i = 0; i < TAPS_PER_GROUP; i++) {
        float4 v = p[(size_t)i * N_VEC];
        float  w = k[t0 + i];
        acc.x += v.x * w;
        acc.y += v.y * w;
        acc.z += v.z * w;
        acc.w += v.w * w;
    }
    // leftover tap (161 = 16*10 + 1) handled by the last group
    if (g == GROUPS - 1) {
        float4 v = p[(size_t)TAPS_PER_GROUP * N_VEC];
        float  w = k[TAPS - 1];
        acc.x += v.x * w;
        acc.y += v.y * w;
        acc.z += v.z * w;
        acc.w += v.w * w;
    }

    if (g > 0) {
        partial[g - 1][nl] = acc;
    }
    __syncthreads();

    if (g == 0) {
        #pragma unroll
        for (int j = 0; j < GROUPS - 1; j++) {
            float4 v = partial[j][nl];
            acc.x += v.x;
            acc.y += v.y;
            acc.z += v.z;
            acc.w += v.w;
        }
        out[vidx] = acc;
    }
}

extern "C" void kernel_launch(void* const* d_in, const int* in_sizes, int n_in,
                              void* d_out, int out_size)
{
    const float4* x = (const float4*)d_in[0];
    float4* out = (float4*)d_out;

    const int blocks = (B_DIM * N_DIM / 4) / VEC_PER_BLOCK;   // 1024

    gaussian_smooth_kernel<<<blocks, BLOCK_THREADS>>>(x, out);
}